// round 2
// baseline (speedup 1.0000x reference)
#include <cuda_runtime.h>
#include <cuda_bf16.h>
#include <math.h>
#include <float.h>

// Problem constants (fixed shapes from reference)
#define Bq   4
#define Tq   16
#define Sq   4096
#define Hq   32
#define KVq  8
#define Dq   128
#define DIMq 4096
#define HD   (Hq*Dq)          // 4096
#define KVD  (KVq*Dq)         // 1024
#define NTOT (HD + 2*KVD)     // 6144
#define M64  (Bq*Tq)          // 64
#define GQ   (Hq/KVq)         // 4
#define AROWS 64              // GQ*Tq rows per (b,kv)
#define NSPLIT 8
#define STILE 32
#define SCALE_F 0.08838834764831843f   // 1/sqrt(128)

// ---------------- scratch (static device globals; no allocation) ------------
__device__ float g_qkv [M64 * NTOT];                       // 1.5 MB   [m][n]
__device__ float g_qatt[Bq*KVq*AROWS*Dq];                  // 1 MB     roped+scaled q
__device__ float g_knew[M64*KVq*Dq];                       // 256 KB   roped new k
__device__ float g_pacc[(size_t)NSPLIT*Bq*KVq*AROWS*Dq];   // 8 MB
__device__ float g_pm  [NSPLIT*Bq*KVq*AROWS];
__device__ float g_pl  [NSPLIT*Bq*KVq*AROWS];
__device__ float g_y   [M64 * HD];                         // 1 MB

// ---------------- generic 64xN GEMM tile:  C[m][n] = sum_k A[m][k]*W[n][k] --
// Block computes 64 rows x 64 cols. 256 threads, 4x4 microtiles, K step 16.
// Fill path: one float4 (16B) global load per thread per operand per K-tile.
__device__ __forceinline__ void gemm_tile(const float* __restrict__ A,
                                          const float* __restrict__ W,
                                          float* __restrict__ Cbase,
                                          int ldc, int K) {
    __shared__ float As[16][68];
    __shared__ float Ws[16][68];
    const int tid = threadIdx.x;
    const int tx = tid & 15, ty = tid >> 4;
    const int fm = tid >> 2;        // 0..63 row for fill
    const int fk = (tid & 3) * 4;   // k-offset 0,4,8,12
    float acc[4][4];
#pragma unroll
    for (int i = 0; i < 4; i++)
#pragma unroll
        for (int j = 0; j < 4; j++) acc[i][j] = 0.f;

    for (int k0 = 0; k0 < K; k0 += 16) {
        __syncthreads();
        {
            float4 a = *reinterpret_cast<const float4*>(&A[(size_t)fm * K + k0 + fk]);
            float4 w = *reinterpret_cast<const float4*>(&W[(size_t)fm * K + k0 + fk]);
            As[fk + 0][fm] = a.x; As[fk + 1][fm] = a.y;
            As[fk + 2][fm] = a.z; As[fk + 3][fm] = a.w;
            Ws[fk + 0][fm] = w.x; Ws[fk + 1][fm] = w.y;
            Ws[fk + 2][fm] = w.z; Ws[fk + 3][fm] = w.w;
        }
        __syncthreads();
#pragma unroll
        for (int kk = 0; kk < 16; kk++) {
            float4 a = *reinterpret_cast<const float4*>(&As[kk][ty * 4]);
            float4 b = *reinterpret_cast<const float4*>(&Ws[kk][tx * 4]);
            acc[0][0] += a.x*b.x; acc[0][1] += a.x*b.y; acc[0][2] += a.x*b.z; acc[0][3] += a.x*b.w;
            acc[1][0] += a.y*b.x; acc[1][1] += a.y*b.y; acc[1][2] += a.y*b.z; acc[1][3] += a.y*b.w;
            acc[2][0] += a.z*b.x; acc[2][1] += a.z*b.y; acc[2][2] += a.z*b.z; acc[2][3] += a.z*b.w;
            acc[3][0] += a.w*b.x; acc[3][1] += a.w*b.y; acc[3][2] += a.w*b.z; acc[3][3] += a.w*b.w;
        }
    }
#pragma unroll
    for (int i = 0; i < 4; i++)
#pragma unroll
        for (int j = 0; j < 4; j++)
            Cbase[(ty * 4 + i) * (size_t)ldc + tx * 4 + j] = acc[i][j];
}

// ---------------- QKV projection -------------------------------------------
__global__ void qkv_kernel(const float* __restrict__ x,
                           const float* __restrict__ wq,
                           const float* __restrict__ wk,
                           const float* __restrict__ wv) {
    int n0 = blockIdx.x * 64;
    const float* W;
    if (n0 < HD)            W = wq + (size_t)n0 * DIMq;
    else if (n0 < HD + KVD) W = wk + (size_t)(n0 - HD) * DIMq;
    else                    W = wv + (size_t)(n0 - HD - KVD) * DIMq;
    gemm_tile(x, W, g_qkv + n0, NTOT, DIMq);
}

// ---------------- RoPE: q -> g_qatt (scaled), k -> g_knew -------------------
#define QPAIRS (M64*Hq*(Dq/2))   // 131072
#define KPAIRS (M64*KVq*(Dq/2))  // 32768
__global__ void rope_kernel(const float* __restrict__ fc, const float* __restrict__ fs) {
    int idx = blockIdx.x * blockDim.x + threadIdx.x;
    if (idx < QPAIRS) {
        int i = idx & 63;
        int h = (idx >> 6) & (Hq - 1);
        int m = idx >> 11;            // b*T + t
        int t = m & (Tq - 1), b = m >> 4;
        float c = fc[t * 64 + i], s = fs[t * 64 + i];
        const float* p = g_qkv + (size_t)m * NTOT + h * Dq + 2 * i;
        float x0 = p[0], x1 = p[1];
        int kv = h >> 2, hl = h & 3;
        float* q = g_qatt + ((((size_t)b * KVq + kv) * AROWS) + hl * Tq + t) * Dq + 2 * i;
        q[0] = (x0 * c - x1 * s) * SCALE_F;
        q[1] = (x0 * s + x1 * c) * SCALE_F;
    } else if (idx < QPAIRS + KPAIRS) {
        int j = idx - QPAIRS;
        int i = j & 63;
        int kv = (j >> 6) & (KVq - 1);
        int m = j >> 9;
        int t = m & (Tq - 1);
        float c = fc[t * 64 + i], s = fs[t * 64 + i];
        const float* p = g_qkv + (size_t)m * NTOT + HD + kv * Dq + 2 * i;
        float x0 = p[0], x1 = p[1];
        float* k = g_knew + ((size_t)m * KVq + kv) * Dq + 2 * i;
        k[0] = x0 * c - x1 * s;
        k[1] = x0 * s + x1 * c;
    }
}

// ---------------- flash attention, split-KV ---------------------------------
// grid = NSPLIT * B * KV, 256 threads.  Per block: all 64 (g,t) query rows of
// one (b,kv) head, a contiguous s-range.  Online softmax, 32-key tiles.
#define ATTN_SMEM_FLOATS (64*129 + 32*129 + 32*128 + 64*32 + 3*64)
__global__ void attn_kernel(const float* __restrict__ k_cache,
                            const float* __restrict__ v_cache,
                            const int* __restrict__ input_pos) {
    extern __shared__ float sm[];
    float* Qs   = sm;                 // [64][129]
    float* Ks   = Qs + 64 * 129;      // [32][129]
    float* Vs   = Ks + 32 * 129;      // [32][128]
    float* Ps   = Vs + 32 * 128;      // [64][32]
    float* rowm = Ps + 64 * 32;
    float* rowl = rowm + 64;
    float* rowsc = rowl + 64;
    __shared__ int pos_s[Tq];

    const int tid = threadIdx.x;
    const int bk = blockIdx.x % (Bq * KVq);
    const int split = blockIdx.x / (Bq * KVq);
    const int b = bk / KVq, kv = bk % KVq;

    if (tid < Tq) pos_s[tid] = input_pos[tid];
    const float* qsrc = g_qatt + ((size_t)b * KVq + kv) * AROWS * Dq;
    for (int e = tid; e < AROWS * Dq; e += 256) {
        int r = e >> 7, d = e & 127;
        Qs[r * 129 + d] = qsrc[e];
    }
    if (tid < AROWS) { rowm[tid] = -FLT_MAX; rowl[tid] = 0.f; }
    __syncthreads();

    const int limit = pos_s[Tq - 1] + 1;
    const int chunk = (limit + NSPLIT - 1) / NSPLIT;
    const int sbeg = split * chunk;
    const int send = min(sbeg + chunk, limit);
    const int start_pos = pos_s[0];

    float acc[32];
#pragma unroll
    for (int i = 0; i < 32; i++) acc[i] = 0.f;
    const int myd = tid & 127;
    const int roff = tid >> 7;   // 0/1

    for (int s0 = sbeg; s0 < send; s0 += STILE) {
        // ---- load K/V tile (new tokens come from roped scratch) ----
        for (int e = tid; e < STILE * Dq; e += 256) {
            int sl = e >> 7, d = e & 127;
            int s = s0 + sl;
            float kval = 0.f, vval = 0.f;
            if (s < send) {
                if (s >= start_pos && s < start_pos + Tq) {
                    int mi = b * Tq + (s - start_pos);
                    kval = g_knew[((size_t)mi * KVq + kv) * Dq + d];
                    vval = g_qkv[(size_t)mi * NTOT + HD + KVD + kv * Dq + d];
                } else {
                    size_t base = (((size_t)b * Sq + s) * KVq + kv) * Dq + d;
                    kval = k_cache[base];
                    vval = v_cache[base];
                }
            }
            Ks[sl * 129 + d] = kval;
            Vs[sl * 128 + d] = vval;
        }
        __syncthreads();

        // ---- scores: thread computes 2 rows x 4 keys ----
        {
            const int rg = tid >> 3;   // 0..31
            const int sg = tid & 7;    // 0..7
            float sc0[4] = {0.f,0.f,0.f,0.f};
            float sc1[4] = {0.f,0.f,0.f,0.f};
            const float* q0 = &Qs[(rg * 2 + 0) * 129];
            const float* q1 = &Qs[(rg * 2 + 1) * 129];
#pragma unroll 8
            for (int k = 0; k < Dq; k++) {
                float a0 = q0[k], a1 = q1[k];
#pragma unroll
                for (int j = 0; j < 4; j++) {
                    float bb = Ks[(sg * 4 + j) * 129 + k];
                    sc0[j] += a0 * bb;
                    sc1[j] += a1 * bb;
                }
            }
#pragma unroll
            for (int j = 0; j < 4; j++) {
                int s = s0 + sg * 4 + j;
                int r0 = rg * 2, r1 = rg * 2 + 1;
                int ok = (s < send);
                Ps[r0 * STILE + sg * 4 + j] =
                    (ok && s <= pos_s[r0 & 15]) ? sc0[j] : -FLT_MAX;
                Ps[r1 * STILE + sg * 4 + j] =
                    (ok && s <= pos_s[r1 & 15]) ? sc1[j] : -FLT_MAX;
            }
        }
        __syncthreads();

        // ---- online softmax per row ----
        if (tid < AROWS) {
            int r = tid;
            float mold = rowm[r];
            float mx = mold;
#pragma unroll
            for (int j = 0; j < STILE; j++) mx = fmaxf(mx, Ps[r * STILE + j]);
            float scl = __expf(mold - mx);
            float lsum = rowl[r] * scl;
#pragma unroll
            for (int j = 0; j < STILE; j++) {
                float p = __expf(Ps[r * STILE + j] - mx);
                Ps[r * STILE + j] = p;
                lsum += p;
            }
            rowm[r] = mx; rowl[r] = lsum; rowsc[r] = scl;
        }
        __syncthreads();

        // ---- rescale + accumulate P@V (thread owns fixed d, 32 rows) ----
#pragma unroll
        for (int i = 0; i < 32; i++) acc[i] *= rowsc[2 * i + roff];
        for (int sl = 0; sl < STILE; sl++) {
            float v = Vs[sl * 128 + myd];
#pragma unroll
            for (int i = 0; i < 32; i++)
                acc[i] += Ps[(2 * i + roff) * STILE + sl] * v;
        }
        __syncthreads();
    }

    // ---- write split partials ----
    float* pbase = g_pacc + ((size_t)split * Bq * KVq + bk) * AROWS * Dq;
#pragma unroll
    for (int i = 0; i < 32; i++)
        pbase[(2 * i + roff) * Dq + myd] = acc[i];
    if (tid < AROWS) {
        int o = (split * Bq * KVq + bk) * AROWS + tid;
        g_pm[o] = rowm[tid];
        g_pl[o] = rowl[tid];
    }
}

// ---------------- combine splits (log-sum-exp merge) ------------------------
__global__ void combine_kernel() {
    int idx = blockIdx.x * 256 + threadIdx.x;
    if (idx >= Bq * KVq * AROWS * Dq) return;
    int d = idx & 127;
    int r = (idx >> 7) & 63;
    int bk = idx >> 13;
    float M = -FLT_MAX;
#pragma unroll
    for (int sp = 0; sp < NSPLIT; sp++)
        M = fmaxf(M, g_pm[(sp * Bq * KVq + bk) * AROWS + r]);
    float L = 0.f, Y = 0.f;
#pragma unroll
    for (int sp = 0; sp < NSPLIT; sp++) {
        int o = (sp * Bq * KVq + bk) * AROWS + r;
        float w = __expf(g_pm[o] - M);
        L += g_pl[o] * w;
        Y += g_pacc[(size_t)o * Dq + d] * w;
    }
    float y = Y / L;
    int b = bk >> 3, kv = bk & 7;
    int hl = r >> 4, t = r & 15;
    int h = kv * GQ + hl;
    int m = b * Tq + t;
    g_y[(size_t)m * HD + h * Dq + d] = y;
}

// ---------------- output projection -----------------------------------------
__global__ void out_kernel(const float* __restrict__ wo, float* __restrict__ out) {
    int n0 = blockIdx.x * 64;
    gemm_tile(g_y, wo + (size_t)n0 * DIMq, out + n0, DIMq, HD);
}

// ---------------- launch -----------------------------------------------------
extern "C" void kernel_launch(void* const* d_in, const int* in_sizes, int n_in,
                              void* d_out, int out_size) {
    const float* x  = (const float*)d_in[0];
    const float* fc = (const float*)d_in[1];
    const float* fs = (const float*)d_in[2];
    const int*  pos = (const int*)  d_in[3];
    // d_in[4] attn_mask unused (mask derived from input_pos)
    const float* kc = (const float*)d_in[5];
    const float* vc = (const float*)d_in[6];
    const float* wq = (const float*)d_in[7];
    const float* wk = (const float*)d_in[8];
    const float* wv = (const float*)d_in[9];
    const float* wo = (const float*)d_in[10];
    float* out = (float*)d_out;

    cudaFuncSetAttribute(attn_kernel, cudaFuncAttributeMaxDynamicSharedMemorySize,
                         ATTN_SMEM_FLOATS * (int)sizeof(float));

    qkv_kernel<<<NTOT / 64, 256>>>(x, wq, wk, wv);
    rope_kernel<<<(QPAIRS + KPAIRS + 255) / 256, 256>>>(fc, fs);
    attn_kernel<<<NSPLIT * Bq * KVq, 256, ATTN_SMEM_FLOATS * sizeof(float)>>>(kc, vc, pos);
    combine_kernel<<<(Bq * KVq * AROWS * Dq + 255) / 256, 256>>>();
    out_kernel<<<DIMq / 64, 256>>>(wo, out);
}

// round 3
// speedup vs baseline: 2.1552x; 2.1552x over previous
#include <cuda_runtime.h>
#include <cuda_bf16.h>
#include <math.h>
#include <float.h>

// Problem constants (fixed shapes from reference)
#define Bq   4
#define Tq   16
#define Sq   4096
#define Hq   32
#define KVq  8
#define Dq   128
#define DIMq 4096
#define HD   (Hq*Dq)          // 4096
#define KVD  (KVq*Dq)         // 1024
#define NTOT (HD + 2*KVD)     // 6144
#define M64  (Bq*Tq)          // 64
#define GQ   (Hq/KVq)         // 4
#define AROWS 64              // GQ*Tq rows per (b,kv)
#define NSPLIT 8
#define STILE 32
#define SCALE_F 0.08838834764831843f   // 1/sqrt(128)

// ---------------- scratch (static device globals; no allocation) ------------
__device__ float g_qkv [M64 * NTOT];                       // 1.5 MB   [m][n]
__device__ float g_qatt[Bq*KVq*AROWS*Dq];                  // 1 MB     roped+scaled q
__device__ float g_knew[M64*KVq*Dq];                       // 256 KB   roped new k
__device__ float g_pacc[(size_t)NSPLIT*Bq*KVq*AROWS*Dq];   // 8 MB
__device__ float g_pm  [NSPLIT*Bq*KVq*AROWS];
__device__ float g_pl  [NSPLIT*Bq*KVq*AROWS];
__device__ float g_y   [M64 * HD];                         // 1 MB

// ================= tensor-core GEMM (tf32 mma.sync) =========================
// C[64][Nblk=64] = A[64][4096] * W[64n][4096k]^T  per block.
// 8 warps (2 m x 4 n), warp tile 32x16, mma m16n8k8, BK=32, 4-stage cp.async.
#define BKg      32
#define GSTAGES  4
#define GSTRIDE  36                        // floats per smem row (pad)
#define GSTG_FLT (2 * 64 * GSTRIDE)        // floats per stage (A + W)
#define GEMM_SMEM_BYTES (GSTAGES * GSTG_FLT * 4)
#define GK       4096
#define GNK      (GK / BKg)                // 128 K-steps

__device__ __forceinline__ unsigned smem_u32(const void* p) {
    unsigned a;
    asm("{ .reg .u64 t; cvta.to.shared.u64 t, %1; cvt.u32.u64 %0, t; }"
        : "=r"(a) : "l"(p));
    return a;
}
__device__ __forceinline__ unsigned f2tf32(float x) {
    unsigned u; asm("cvt.rna.tf32.f32 %0, %1;" : "=r"(u) : "f"(x)); return u;
}
__device__ __forceinline__ void mma_tf32(float c[4], const unsigned a[4], const unsigned b[2]) {
    asm volatile(
        "mma.sync.aligned.m16n8k8.row.col.f32.tf32.tf32.f32 "
        "{%0,%1,%2,%3}, {%4,%5,%6,%7}, {%8,%9}, {%0,%1,%2,%3};\n"
        : "+f"(c[0]), "+f"(c[1]), "+f"(c[2]), "+f"(c[3])
        : "r"(a[0]), "r"(a[1]), "r"(a[2]), "r"(a[3]), "r"(b[0]), "r"(b[1]));
}
__device__ __forceinline__ void cpasync16(unsigned saddr, const float* g) {
    asm volatile("cp.async.ca.shared.global [%0], [%1], 16;" :: "r"(saddr), "l"(g));
}

__device__ __forceinline__ void gemm_tile_mma(const float* __restrict__ A,
                                              const float* __restrict__ W,
                                              float* __restrict__ Cbase,
                                              int ldc) {
    extern __shared__ float smf[];
    const int tid  = threadIdx.x;
    const int lane = tid & 31;
    const int wid  = tid >> 5;
    const int gid  = lane >> 2;      // 0..7
    const int ctg  = lane & 3;       // 0..3
    const int wm   = wid & 1;        // 2 warp-rows
    const int wn   = wid >> 1;       // 4 warp-cols
    const int frow = tid >> 2;       // 0..63 fill row
    const int fk   = (tid & 3) * 8;  // fill k offset (8 floats/thread/operand)
    const unsigned sbase = smem_u32(smf);

    float acc[2][2][4];
#pragma unroll
    for (int mi = 0; mi < 2; mi++)
#pragma unroll
        for (int ni = 0; ni < 2; ni++)
#pragma unroll
            for (int j = 0; j < 4; j++) acc[mi][ni][j] = 0.f;

    // prologue: prefetch stages 0..2
#pragma unroll
    for (int s = 0; s < GSTAGES - 1; s++) {
        unsigned sa = sbase + (unsigned)(s * GSTG_FLT + frow * GSTRIDE + fk) * 4u;
        unsigned sw = sa + 64u * GSTRIDE * 4u;
        const float* ga = A + (size_t)frow * GK + s * BKg + fk;
        const float* gw = W + (size_t)frow * GK + s * BKg + fk;
        cpasync16(sa, ga);       cpasync16(sa + 16, ga + 4);
        cpasync16(sw, gw);       cpasync16(sw + 16, gw + 4);
        asm volatile("cp.async.commit_group;");
    }

    for (int i = 0; i < GNK; i++) {
        asm volatile("cp.async.wait_group 2;");
        __syncthreads();
        const float* As = smf + (i & 3) * GSTG_FLT;
        const float* Ws = As + 64 * GSTRIDE;

#pragma unroll
        for (int ks = 0; ks < 4; ks++) {
            const int k = ks * 8;
            unsigned af[2][4], bf[2][2];
#pragma unroll
            for (int mi = 0; mi < 2; mi++) {
                int r = wm * 32 + mi * 16 + gid;
                af[mi][0] = f2tf32(As[r * GSTRIDE + k + ctg]);
                af[mi][1] = f2tf32(As[(r + 8) * GSTRIDE + k + ctg]);
                af[mi][2] = f2tf32(As[r * GSTRIDE + k + ctg + 4]);
                af[mi][3] = f2tf32(As[(r + 8) * GSTRIDE + k + ctg + 4]);
            }
#pragma unroll
            for (int ni = 0; ni < 2; ni++) {
                int n = wn * 16 + ni * 8 + gid;
                bf[ni][0] = f2tf32(Ws[n * GSTRIDE + k + ctg]);
                bf[ni][1] = f2tf32(Ws[n * GSTRIDE + k + ctg + 4]);
            }
#pragma unroll
            for (int mi = 0; mi < 2; mi++)
#pragma unroll
                for (int ni = 0; ni < 2; ni++)
                    mma_tf32(acc[mi][ni], af[mi], bf[ni]);
        }

        // prefetch stage i+3 (or empty commit to keep group bookkeeping)
        if (i + GSTAGES - 1 < GNK) {
            int s = (i + 3) & 3;
            int k0 = (i + 3) * BKg;
            unsigned sa = sbase + (unsigned)(s * GSTG_FLT + frow * GSTRIDE + fk) * 4u;
            unsigned sw = sa + 64u * GSTRIDE * 4u;
            const float* ga = A + (size_t)frow * GK + k0 + fk;
            const float* gw = W + (size_t)frow * GK + k0 + fk;
            cpasync16(sa, ga);       cpasync16(sa + 16, ga + 4);
            cpasync16(sw, gw);       cpasync16(sw + 16, gw + 4);
            asm volatile("cp.async.commit_group;");
        } else {
            asm volatile("cp.async.commit_group;");
        }
    }

    // epilogue: write fp32 accumulators
#pragma unroll
    for (int mi = 0; mi < 2; mi++)
#pragma unroll
        for (int ni = 0; ni < 2; ni++) {
            int r0 = wm * 32 + mi * 16 + gid;
            int c0 = wn * 16 + ni * 8 + 2 * ctg;
            *reinterpret_cast<float2*>(&Cbase[(size_t)r0 * ldc + c0]) =
                make_float2(acc[mi][ni][0], acc[mi][ni][1]);
            *reinterpret_cast<float2*>(&Cbase[(size_t)(r0 + 8) * ldc + c0]) =
                make_float2(acc[mi][ni][2], acc[mi][ni][3]);
        }
}

// ---------------- QKV projection -------------------------------------------
__global__ void qkv_kernel(const float* __restrict__ x,
                           const float* __restrict__ wq,
                           const float* __restrict__ wk,
                           const float* __restrict__ wv) {
    int n0 = blockIdx.x * 64;
    const float* W;
    if (n0 < HD)            W = wq + (size_t)n0 * DIMq;
    else if (n0 < HD + KVD) W = wk + (size_t)(n0 - HD) * DIMq;
    else                    W = wv + (size_t)(n0 - HD - KVD) * DIMq;
    gemm_tile_mma(x, W, g_qkv + n0, NTOT);
}

// ---------------- output projection -----------------------------------------
__global__ void out_kernel(const float* __restrict__ wo, float* __restrict__ out) {
    int n0 = blockIdx.x * 64;
    gemm_tile_mma(g_y, wo + (size_t)n0 * DIMq, out + n0, DIMq);
}

// ---------------- RoPE: q -> g_qatt (scaled), k -> g_knew -------------------
#define QPAIRS (M64*Hq*(Dq/2))   // 131072
#define KPAIRS (M64*KVq*(Dq/2))  // 32768
__global__ void rope_kernel(const float* __restrict__ fc, const float* __restrict__ fs) {
    int idx = blockIdx.x * blockDim.x + threadIdx.x;
    if (idx < QPAIRS) {
        int i = idx & 63;
        int h = (idx >> 6) & (Hq - 1);
        int m = idx >> 11;            // b*T + t
        int t = m & (Tq - 1), b = m >> 4;
        float c = fc[t * 64 + i], s = fs[t * 64 + i];
        const float* p = g_qkv + (size_t)m * NTOT + h * Dq + 2 * i;
        float x0 = p[0], x1 = p[1];
        int kv = h >> 2, hl = h & 3;
        float* q = g_qatt + ((((size_t)b * KVq + kv) * AROWS) + hl * Tq + t) * Dq + 2 * i;
        q[0] = (x0 * c - x1 * s) * SCALE_F;
        q[1] = (x0 * s + x1 * c) * SCALE_F;
    } else if (idx < QPAIRS + KPAIRS) {
        int j = idx - QPAIRS;
        int i = j & 63;
        int kv = (j >> 6) & (KVq - 1);
        int m = j >> 9;
        int t = m & (Tq - 1);
        float c = fc[t * 64 + i], s = fs[t * 64 + i];
        const float* p = g_qkv + (size_t)m * NTOT + HD + kv * Dq + 2 * i;
        float x0 = p[0], x1 = p[1];
        float* k = g_knew + ((size_t)m * KVq + kv) * Dq + 2 * i;
        k[0] = x0 * c - x1 * s;
        k[1] = x0 * s + x1 * c;
    }
}

// ---------------- flash attention, split-KV ---------------------------------
#define ATTN_SMEM_FLOATS (64*129 + 32*129 + 32*128 + 64*32 + 3*64)
__global__ void attn_kernel(const float* __restrict__ k_cache,
                            const float* __restrict__ v_cache,
                            const int* __restrict__ input_pos) {
    extern __shared__ float sm[];
    float* Qs   = sm;                 // [64][129]
    float* Ks   = Qs + 64 * 129;      // [32][129]
    float* Vs   = Ks + 32 * 129;      // [32][128]
    float* Ps   = Vs + 32 * 128;      // [64][32]
    float* rowm = Ps + 64 * 32;
    float* rowl = rowm + 64;
    float* rowsc = rowl + 64;
    __shared__ int pos_s[Tq];

    const int tid = threadIdx.x;
    const int bk = blockIdx.x % (Bq * KVq);
    const int split = blockIdx.x / (Bq * KVq);
    const int b = bk / KVq, kv = bk % KVq;

    if (tid < Tq) pos_s[tid] = input_pos[tid];
    const float* qsrc = g_qatt + ((size_t)b * KVq + kv) * AROWS * Dq;
    for (int e = tid; e < AROWS * Dq; e += 256) {
        int r = e >> 7, d = e & 127;
        Qs[r * 129 + d] = qsrc[e];
    }
    if (tid < AROWS) { rowm[tid] = -FLT_MAX; rowl[tid] = 0.f; }
    __syncthreads();

    const int limit = pos_s[Tq - 1] + 1;
    const int chunk = (limit + NSPLIT - 1) / NSPLIT;
    const int sbeg = split * chunk;
    const int send = min(sbeg + chunk, limit);
    const int start_pos = pos_s[0];

    float acc[32];
#pragma unroll
    for (int i = 0; i < 32; i++) acc[i] = 0.f;
    const int myd = tid & 127;
    const int roff = tid >> 7;   // 0/1

    for (int s0 = sbeg; s0 < send; s0 += STILE) {
        for (int e = tid; e < STILE * Dq; e += 256) {
            int sl = e >> 7, d = e & 127;
            int s = s0 + sl;
            float kval = 0.f, vval = 0.f;
            if (s < send) {
                if (s >= start_pos && s < start_pos + Tq) {
                    int mi = b * Tq + (s - start_pos);
                    kval = g_knew[((size_t)mi * KVq + kv) * Dq + d];
                    vval = g_qkv[(size_t)mi * NTOT + HD + KVD + kv * Dq + d];
                } else {
                    size_t base = (((size_t)b * Sq + s) * KVq + kv) * Dq + d;
                    kval = k_cache[base];
                    vval = v_cache[base];
                }
            }
            Ks[sl * 129 + d] = kval;
            Vs[sl * 128 + d] = vval;
        }
        __syncthreads();

        {
            const int rg = tid >> 3;   // 0..31
            const int sg = tid & 7;    // 0..7
            float sc0[4] = {0.f,0.f,0.f,0.f};
            float sc1[4] = {0.f,0.f,0.f,0.f};
            const float* q0 = &Qs[(rg * 2 + 0) * 129];
            const float* q1 = &Qs[(rg * 2 + 1) * 129];
#pragma unroll 8
            for (int k = 0; k < Dq; k++) {
                float a0 = q0[k], a1 = q1[k];
#pragma unroll
                for (int j = 0; j < 4; j++) {
                    float bb = Ks[(sg * 4 + j) * 129 + k];
                    sc0[j] += a0 * bb;
                    sc1[j] += a1 * bb;
                }
            }
#pragma unroll
            for (int j = 0; j < 4; j++) {
                int s = s0 + sg * 4 + j;
                int r0 = rg * 2, r1 = rg * 2 + 1;
                int ok = (s < send);
                Ps[r0 * STILE + sg * 4 + j] =
                    (ok && s <= pos_s[r0 & 15]) ? sc0[j] : -FLT_MAX;
                Ps[r1 * STILE + sg * 4 + j] =
                    (ok && s <= pos_s[r1 & 15]) ? sc1[j] : -FLT_MAX;
            }
        }
        __syncthreads();

        if (tid < AROWS) {
            int r = tid;
            float mold = rowm[r];
            float mx = mold;
#pragma unroll
            for (int j = 0; j < STILE; j++) mx = fmaxf(mx, Ps[r * STILE + j]);
            float scl = __expf(mold - mx);
            float lsum = rowl[r] * scl;
#pragma unroll
            for (int j = 0; j < STILE; j++) {
                float p = __expf(Ps[r * STILE + j] - mx);
                Ps[r * STILE + j] = p;
                lsum += p;
            }
            rowm[r] = mx; rowl[r] = lsum; rowsc[r] = scl;
        }
        __syncthreads();

#pragma unroll
        for (int i = 0; i < 32; i++) acc[i] *= rowsc[2 * i + roff];
        for (int sl = 0; sl < STILE; sl++) {
            float v = Vs[sl * 128 + myd];
#pragma unroll
            for (int i = 0; i < 32; i++)
                acc[i] += Ps[(2 * i + roff) * STILE + sl] * v;
        }
        __syncthreads();
    }

    float* pbase = g_pacc + ((size_t)split * Bq * KVq + bk) * AROWS * Dq;
#pragma unroll
    for (int i = 0; i < 32; i++)
        pbase[(2 * i + roff) * Dq + myd] = acc[i];
    if (tid < AROWS) {
        int o = (split * Bq * KVq + bk) * AROWS + tid;
        g_pm[o] = rowm[tid];
        g_pl[o] = rowl[tid];
    }
}

// ---------------- combine splits (log-sum-exp merge) ------------------------
__global__ void combine_kernel() {
    int idx = blockIdx.x * 256 + threadIdx.x;
    if (idx >= Bq * KVq * AROWS * Dq) return;
    int d = idx & 127;
    int r = (idx >> 7) & 63;
    int bk = idx >> 13;
    float M = -FLT_MAX;
#pragma unroll
    for (int sp = 0; sp < NSPLIT; sp++)
        M = fmaxf(M, g_pm[(sp * Bq * KVq + bk) * AROWS + r]);
    float L = 0.f, Y = 0.f;
#pragma unroll
    for (int sp = 0; sp < NSPLIT; sp++) {
        int o = (sp * Bq * KVq + bk) * AROWS + r;
        float w = __expf(g_pm[o] - M);
        L += g_pl[o] * w;
        Y += g_pacc[(size_t)o * Dq + d] * w;
    }
    float y = Y / L;
    int b = bk >> 3, kv = bk & 7;
    int hl = r >> 4, t = r & 15;
    int h = kv * GQ + hl;
    int m = b * Tq + t;
    g_y[(size_t)m * HD + h * Dq + d] = y;
}

// ---------------- launch -----------------------------------------------------
extern "C" void kernel_launch(void* const* d_in, const int* in_sizes, int n_in,
                              void* d_out, int out_size) {
    const float* x  = (const float*)d_in[0];
    const float* fc = (const float*)d_in[1];
    const float* fs = (const float*)d_in[2];
    const int*  pos = (const int*)  d_in[3];
    // d_in[4] attn_mask unused (mask derived from input_pos)
    const float* kc = (const float*)d_in[5];
    const float* vc = (const float*)d_in[6];
    const float* wq = (const float*)d_in[7];
    const float* wk = (const float*)d_in[8];
    const float* wv = (const float*)d_in[9];
    const float* wo = (const float*)d_in[10];
    float* out = (float*)d_out;

    cudaFuncSetAttribute(attn_kernel, cudaFuncAttributeMaxDynamicSharedMemorySize,
                         ATTN_SMEM_FLOATS * (int)sizeof(float));
    cudaFuncSetAttribute(qkv_kernel, cudaFuncAttributeMaxDynamicSharedMemorySize,
                         GEMM_SMEM_BYTES);
    cudaFuncSetAttribute(out_kernel, cudaFuncAttributeMaxDynamicSharedMemorySize,
                         GEMM_SMEM_BYTES);

    qkv_kernel<<<NTOT / 64, 256, GEMM_SMEM_BYTES>>>(x, wq, wk, wv);
    rope_kernel<<<(QPAIRS + KPAIRS + 255) / 256, 256>>>(fc, fs);
    attn_kernel<<<NSPLIT * Bq * KVq, 256, ATTN_SMEM_FLOATS * sizeof(float)>>>(kc, vc, pos);
    combine_kernel<<<(Bq * KVq * AROWS * Dq + 255) / 256, 256>>>();
    out_kernel<<<DIMq / 64, 256, GEMM_SMEM_BYTES>>>(wo, out);
}